// round 2
// baseline (speedup 1.0000x reference)
#include <cuda_runtime.h>
#include <math.h>

#define NSEQ 384
#define D 128
#define MROWS (NSEQ*NSEQ)   // 147456

// Scratch (allocation-free rule: __device__ globals)
__device__ float g_xn[MROWS*D];                 // layernormed x, row-major [m][d]
__device__ float g_left[(size_t)D*MROWS];       // transposed [d][k*384+j]
__device__ float g_right[(size_t)D*MROWS];      // transposed [d][k*384+i]
__device__ float g_gate[MROWS*D];               // row-major [m][d]
__device__ float g_tri[(size_t)D*MROWS];        // einsum out, [d][i*384+j]

__device__ __forceinline__ float sigf(float x) {
    return 1.0f / (1.0f + __expf(-x));
}

// ---------------------------------------------------------------------------
// Kernel 1: input layernorm.  1 warp per row of 128.
// ---------------------------------------------------------------------------
__global__ void ln_kernel(const float* __restrict__ x,
                          const float* __restrict__ na,
                          const float* __restrict__ nb) {
    int m = blockIdx.x * 8 + (threadIdx.x >> 5);
    int lane = threadIdx.x & 31;
    const float4* xr = reinterpret_cast<const float4*>(x + (size_t)m * D);
    float4 v = xr[lane];
    float s = v.x + v.y + v.z + v.w;
    float q = v.x*v.x + v.y*v.y + v.z*v.z + v.w*v.w;
    #pragma unroll
    for (int o = 16; o > 0; o >>= 1) {
        s += __shfl_xor_sync(0xffffffffu, s, o);
        q += __shfl_xor_sync(0xffffffffu, q, o);
    }
    float mean = s * (1.0f/128.0f);
    float var  = q * (1.0f/128.0f) - mean*mean;
    float rstd = rsqrtf(var + 1e-5f);
    int d0 = lane * 4;
    float4 o4;
    o4.x = na[d0+0]*(v.x-mean)*rstd + nb[d0+0];
    o4.y = na[d0+1]*(v.y-mean)*rstd + nb[d0+1];
    o4.z = na[d0+2]*(v.z-mean)*rstd + nb[d0+2];
    o4.w = na[d0+3]*(v.w-mean)*rstd + nb[d0+3];
    reinterpret_cast<float4*>(g_xn + (size_t)m * D)[lane] = o4;
}

// ---------------------------------------------------------------------------
// Kernel 2: projections.  blockIdx.z: 0=left, 1=right, 2=out_gate.
// Computes xn@W1+b1 (and xn@W2+b2 for gated types), applies sigmoid gating.
// left/right written d-major transposed for the einsum (via smem transpose so
// global stores are coalesced along m); gate row-major.
// Tile: BM=64 BN=64 BK=32, 256 threads, 4x4 microtile (strided 16).
// ---------------------------------------------------------------------------
__global__ void proj_kernel(const float* __restrict__ Wl,  const float* __restrict__ bl,
                            const float* __restrict__ Wlg, const float* __restrict__ blg,
                            const float* __restrict__ Wr,  const float* __restrict__ br,
                            const float* __restrict__ Wrg, const float* __restrict__ brg,
                            const float* __restrict__ Wog, const float* __restrict__ bog) {
    __shared__ float As[32][65];   // [k][m], padded
    __shared__ float Bs1[32][64];  // [k][n]
    __shared__ float Bs2[32][64];
    __shared__ float Tr[64][68];   // transpose staging [c][m], padded

    int type = blockIdx.z;
    const float *W1, *B1, *W2, *B2;
    if (type == 0)      { W1 = Wl;  B1 = bl;  W2 = Wlg; B2 = blg; }
    else if (type == 1) { W1 = Wr;  B1 = br;  W2 = Wrg; B2 = brg; }
    else                { W1 = Wog; B1 = bog; W2 = Wog; B2 = bog; }
    bool dual = (type < 2);

    int m0 = blockIdx.x * 64;
    int n0 = blockIdx.y * 64;
    int tid = threadIdx.x;
    int tx = tid & 15, ty = tid >> 4;

    float acc1[4][4] = {};
    float acc2[4][4] = {};

    for (int k0 = 0; k0 < 128; k0 += 32) {
        // A tile: 64 rows x 32 k, transpose into As[k][m]
        {
            int c = tid & 31, r0 = tid >> 5;
            #pragma unroll
            for (int l = 0; l < 8; l++) {
                int r = r0 + l * 8;
                As[c][r] = g_xn[(m0 + r) * 128 + k0 + c];
            }
        }
        // B tiles: 32 k x 64 n, direct
        {
            int cc = tid & 63, kk0 = tid >> 6;
            #pragma unroll
            for (int l = 0; l < 8; l++) {
                int kk = kk0 + l * 4;
                Bs1[kk][cc] = W1[(k0 + kk) * 128 + n0 + cc];
                if (dual) Bs2[kk][cc] = W2[(k0 + kk) * 128 + n0 + cc];
            }
        }
        __syncthreads();

        if (dual) {
            #pragma unroll
            for (int kk = 0; kk < 32; kk++) {
                float a[4], b1v[4], b2v[4];
                #pragma unroll
                for (int i = 0; i < 4; i++) a[i] = As[kk][ty + 16*i];
                #pragma unroll
                for (int j = 0; j < 4; j++) { b1v[j] = Bs1[kk][tx + 16*j]; b2v[j] = Bs2[kk][tx + 16*j]; }
                #pragma unroll
                for (int i = 0; i < 4; i++)
                    #pragma unroll
                    for (int j = 0; j < 4; j++) {
                        acc1[i][j] += a[i] * b1v[j];
                        acc2[i][j] += a[i] * b2v[j];
                    }
            }
        } else {
            #pragma unroll
            for (int kk = 0; kk < 32; kk++) {
                float a[4], b1v[4];
                #pragma unroll
                for (int i = 0; i < 4; i++) a[i] = As[kk][ty + 16*i];
                #pragma unroll
                for (int j = 0; j < 4; j++) b1v[j] = Bs1[kk][tx + 16*j];
                #pragma unroll
                for (int i = 0; i < 4; i++)
                    #pragma unroll
                    for (int j = 0; j < 4; j++)
                        acc1[i][j] += a[i] * b1v[j];
            }
        }
        __syncthreads();
    }

    if (type < 2) {
        float* dst = (type == 0) ? g_left : g_right;
        // gated value into transpose staging: Tr[c_local][m_local]
        #pragma unroll
        for (int i = 0; i < 4; i++) {
            #pragma unroll
            for (int j = 0; j < 4; j++) {
                int c = n0 + tx + 16*j;
                float v = (acc1[i][j] + B1[c]) * sigf(acc2[i][j] + B2[c]);
                Tr[tx + 16*j][ty + 16*i] = v;
            }
        }
        __syncthreads();
        // coalesced store: for each output channel c, m0..m0+63 is contiguous
        // 256 threads * 4 iters, float4 each: 64 cols x 16 float4
        #pragma unroll
        for (int l = 0; l < 4; l++) {
            int idx = tid + l * 256;          // 0..1023
            int cl = idx >> 4;                // 0..63
            int q  = idx & 15;                // 0..15 (float4 index within 64 m)
            float4 v4;
            v4.x = Tr[cl][q*4+0];
            v4.y = Tr[cl][q*4+1];
            v4.z = Tr[cl][q*4+2];
            v4.w = Tr[cl][q*4+3];
            reinterpret_cast<float4*>(dst + (size_t)(n0 + cl) * MROWS + m0)[q] = v4;
        }
    } else {
        #pragma unroll
        for (int i = 0; i < 4; i++) {
            int m = m0 + ty + 16*i;
            #pragma unroll
            for (int j = 0; j < 4; j++) {
                int c = n0 + tx + 16*j;
                g_gate[(size_t)m * 128 + c] = sigf(acc1[i][j] + B1[c]);
            }
        }
    }
}

// ---------------------------------------------------------------------------
// Kernel 3: einsum.  For each d: O[i,j] = (1/n) sum_k R[k,i] * L[k,j].
// Both operands k-major (no transpose needed).  128 batched 384^3 SGEMMs.
// ---------------------------------------------------------------------------
__global__ void einsum_kernel() {
    __shared__ float As[32][64];  // right: [k][i]
    __shared__ float Bs[32][64];  // left:  [k][j]
    int d = blockIdx.z;
    int i0 = blockIdx.y * 64;
    int j0 = blockIdx.x * 64;
    const float* R = g_right + (size_t)d * MROWS;
    const float* L = g_left  + (size_t)d * MROWS;
    int tid = threadIdx.x;
    int tx = tid & 15, ty = tid >> 4;
    float acc[4][4] = {};

    for (int k0 = 0; k0 < NSEQ; k0 += 32) {
        int cc = tid & 63, kk0 = tid >> 6;
        #pragma unroll
        for (int l = 0; l < 8; l++) {
            int kk = kk0 + l * 4;
            As[kk][cc] = R[(k0 + kk) * NSEQ + i0 + cc];
            Bs[kk][cc] = L[(k0 + kk) * NSEQ + j0 + cc];
        }
        __syncthreads();
        #pragma unroll
        for (int kk = 0; kk < 32; kk++) {
            float a[4], b[4];
            #pragma unroll
            for (int i = 0; i < 4; i++) a[i] = As[kk][ty + 16*i];
            #pragma unroll
            for (int j = 0; j < 4; j++) b[j] = Bs[kk][tx + 16*j];
            #pragma unroll
            for (int i = 0; i < 4; i++)
                #pragma unroll
                for (int j = 0; j < 4; j++)
                    acc[i][j] += a[i] * b[j];
        }
        __syncthreads();
    }

    const float scale = 1.0f / (float)NSEQ;
    float* O = g_tri + (size_t)d * MROWS;
    #pragma unroll
    for (int i = 0; i < 4; i++)
        #pragma unroll
        for (int j = 0; j < 4; j++)
            O[(i0 + ty + 16*i) * NSEQ + j0 + tx + 16*j] = acc[i][j] * scale;
}

// ---------------------------------------------------------------------------
// Kernel 4: output LN over d (gathered from d-major g_tri), * gate, @ Wo + bo.
// BM=64 rows staged in shared, BN=64 output cols, BK=32.
// ---------------------------------------------------------------------------
__global__ void final_kernel(const float* __restrict__ ona,
                             const float* __restrict__ onb,
                             const float* __restrict__ Wo,
                             const float* __restrict__ bo,
                             float* __restrict__ out) {
    __shared__ float V[64][129];
    __shared__ float Ws[32][64];
    int m0 = blockIdx.x * 64;
    int n0 = blockIdx.y * 64;
    int tid = threadIdx.x;

    // gather 64 rows x 128 d (coalesced per d-slice)
    for (int idx = tid; idx < 64 * 128; idx += 256) {
        int d = idx >> 6;
        int r = idx & 63;
        V[r][d] = g_tri[(size_t)d * MROWS + m0 + r];
    }
    __syncthreads();

    // per-row layernorm + gate: 8 warps x 8 rows
    int lane = tid & 31, w = tid >> 5;
    for (int rr = 0; rr < 8; rr++) {
        int r = w * 8 + rr;
        float vals[4];
        float s = 0.f, q = 0.f;
        #pragma unroll
        for (int t = 0; t < 4; t++) {
            float v = V[r][lane + 32*t];
            vals[t] = v; s += v; q += v*v;
        }
        #pragma unroll
        for (int o = 16; o > 0; o >>= 1) {
            s += __shfl_xor_sync(0xffffffffu, s, o);
            q += __shfl_xor_sync(0xffffffffu, q, o);
        }
        float mean = s * (1.0f/128.0f);
        float var  = q * (1.0f/128.0f) - mean*mean;
        float rstd = rsqrtf(var + 1e-5f);
        #pragma unroll
        for (int t = 0; t < 4; t++) {
            int d = lane + 32*t;
            float v = ona[d]*(vals[t]-mean)*rstd + onb[d];
            v *= g_gate[(size_t)(m0 + r) * 128 + d];
            V[r][d] = v;
        }
    }
    __syncthreads();

    int tx = tid & 15, ty = tid >> 4;
    float acc[4][4] = {};
    for (int k0 = 0; k0 < 128; k0 += 32) {
        int cc = tid & 63, kk0 = tid >> 6;
        #pragma unroll
        for (int l = 0; l < 8; l++) {
            int kk = kk0 + l * 4;
            Ws[kk][cc] = Wo[(k0 + kk) * 128 + n0 + cc];
        }
        __syncthreads();
        #pragma unroll
        for (int kk = 0; kk < 32; kk++) {
            float a[4], b[4];
            #pragma unroll
            for (int i = 0; i < 4; i++) a[i] = V[ty + 16*i][k0 + kk];
            #pragma unroll
            for (int j = 0; j < 4; j++) b[j] = Ws[kk][tx + 16*j];
            #pragma unroll
            for (int i = 0; i < 4; i++)
                #pragma unroll
                for (int j = 0; j < 4; j++)
                    acc[i][j] += a[i] * b[j];
        }
        __syncthreads();
    }

    #pragma unroll
    for (int i = 0; i < 4; i++) {
        int m = m0 + ty + 16*i;
        #pragma unroll
        for (int j = 0; j < 4; j++) {
            int c = n0 + tx + 16*j;
            out[(size_t)m * 128 + c] = acc[i][j] + bo[c];
        }
    }
}

// ---------------------------------------------------------------------------
extern "C" void kernel_launch(void* const* d_in, const int* in_sizes, int n_in,
                              void* d_out, int out_size) {
    const float* x      = (const float*)d_in[0];
    const float* norm_a = (const float*)d_in[1];
    const float* norm_b = (const float*)d_in[2];
    const float* Wl     = (const float*)d_in[3];
    const float* bl     = (const float*)d_in[4];
    const float* Wr     = (const float*)d_in[5];
    const float* br     = (const float*)d_in[6];
    const float* Wlg    = (const float*)d_in[7];
    const float* blg    = (const float*)d_in[8];
    const float* Wrg    = (const float*)d_in[9];
    const float* brg    = (const float*)d_in[10];
    const float* Wog    = (const float*)d_in[11];
    const float* bog    = (const float*)d_in[12];
    const float* on_a   = (const float*)d_in[13];
    const float* on_b   = (const float*)d_in[14];
    const float* Wo     = (const float*)d_in[15];
    const float* bo     = (const float*)d_in[16];
    float* out = (float*)d_out;

    ln_kernel<<<MROWS / 8, 256>>>(x, norm_a, norm_b);
    proj_kernel<<<dim3(MROWS / 64, 2, 3), 256>>>(Wl, bl, Wlg, blg,
                                                 Wr, br, Wrg, brg,
                                                 Wog, bog);
    einsum_kernel<<<dim3(NSEQ / 64, NSEQ / 64, D), 256>>>();
    final_kernel<<<dim3(MROWS / 64, 2), 256>>>(on_a, on_b, Wo, bo, out);
}

// round 6
// speedup vs baseline: 2.0225x; 2.0225x over previous
#include <cuda_runtime.h>
#include <cuda_bf16.h>
#include <stdint.h>

#define NSEQ 384
#define MROWS 147456

__device__ __align__(16) __nv_bfloat16 g_xh[(size_t)MROWS*128];
__device__ __align__(16) __nv_bfloat16 g_xl[(size_t)MROWS*128];
__device__ __align__(16) __nv_bfloat16 g_lh[(size_t)128*MROWS];  // [d][k*384+j]
__device__ __align__(16) __nv_bfloat16 g_ll[(size_t)128*MROWS];
__device__ __align__(16) __nv_bfloat16 g_rh[(size_t)128*MROWS];  // [d][k*384+i]
__device__ __align__(16) __nv_bfloat16 g_rl[(size_t)128*MROWS];
__device__ __align__(16) float g_gate[(size_t)MROWS*128];        // [m][d]
__device__ __align__(16) float g_tri [(size_t)128*MROWS];        // [d][i*384+j]
__device__ __align__(16) __nv_bfloat16 g_wh[6][16384];           // W^T [n][k]
__device__ __align__(16) __nv_bfloat16 g_wl[6][16384];

__device__ __forceinline__ uint32_t s2u(const void* p) {
    uint32_t a;
    asm("{ .reg .u64 t; cvta.to.shared.u64 t, %1; cvt.u32.u64 %0, t; }" : "=r"(a) : "l"(p));
    return a;
}
__device__ __forceinline__ uint32_t sw(int r, int g) {  // 256B rows, 16B granules
    return (uint32_t)(r*256 + ((g ^ (r & 7)) << 4));
}
__device__ __forceinline__ void mma_bf16(float* c, const uint32_t* a, const uint32_t* b) {
    asm volatile("mma.sync.aligned.m16n8k16.row.col.f32.bf16.bf16.f32 "
        "{%0,%1,%2,%3}, {%4,%5,%6,%7}, {%8,%9}, {%0,%1,%2,%3};"
        : "+f"(c[0]), "+f"(c[1]), "+f"(c[2]), "+f"(c[3])
        : "r"(a[0]), "r"(a[1]), "r"(a[2]), "r"(a[3]), "r"(b[0]), "r"(b[1]));
}
__device__ __forceinline__ void ldsm4(uint32_t* r, uint32_t a) {
    asm volatile("ldmatrix.sync.aligned.m8n8.x4.shared.b16 {%0,%1,%2,%3}, [%4];"
        : "=r"(r[0]),"=r"(r[1]),"=r"(r[2]),"=r"(r[3]) : "r"(a));
}
__device__ __forceinline__ void ldsm4t(uint32_t* r, uint32_t a) {
    asm volatile("ldmatrix.sync.aligned.m8n8.x4.trans.shared.b16 {%0,%1,%2,%3}, [%4];"
        : "=r"(r[0]),"=r"(r[1]),"=r"(r[2]),"=r"(r[3]) : "r"(a));
}
__device__ __forceinline__ void stsm4t(uint32_t a, const uint32_t* r) {
    asm volatile("stmatrix.sync.aligned.m8n8.x4.trans.shared.b16 [%0], {%1,%2,%3,%4};"
        :: "r"(a), "r"(r[0]), "r"(r[1]), "r"(r[2]), "r"(r[3]) : "memory");
}
__device__ __forceinline__ void cp16(uint32_t s, const void* g) {
    asm volatile("cp.async.cg.shared.global [%0], [%1], 16;" :: "r"(s), "l"(g));
}
#define CP_COMMIT() asm volatile("cp.async.commit_group;" ::: "memory")
#define CP_WAIT1()  asm volatile("cp.async.wait_group 1;" ::: "memory")
#define CP_WAIT0()  asm volatile("cp.async.wait_group 0;" ::: "memory")

__device__ __forceinline__ float sigf(float x) { return 1.0f/(1.0f+__expf(-x)); }
__device__ __forceinline__ uint32_t pk(float a, float b) {
    __nv_bfloat162 t = __floats2bfloat162_rn(a, b);
    return *reinterpret_cast<uint32_t*>(&t);
}
__device__ __forceinline__ float bfr(float v) { return __bfloat162float(__float2bfloat16(v)); }
__device__ __forceinline__ void split2(float x, __nv_bfloat16& h, __nv_bfloat16& l) {
    h = __float2bfloat16(x);
    l = __float2bfloat16(x - __bfloat162float(h));
}
// load 128x128 bf16 row-major (ld=128) tile into swizzled smem
__device__ __forceinline__ void ldt(char* sm, uint32_t off, const __nv_bfloat16* src, int tid) {
    #pragma unroll
    for (int i = 0; i < 8; i++) {
        int idx = tid + i*256, r = idx>>4, g = idx&15;
        *reinterpret_cast<uint4*>(sm + off + sw(r,g)) =
            *reinterpret_cast<const uint4*>(src + (size_t)r*128 + g*8);
    }
}

// ---------------- kernel 1: LN + split ----------------
__global__ void ln_split(const float* __restrict__ x, const float* __restrict__ na,
                         const float* __restrict__ nb) {
    int m = blockIdx.x*8 + (threadIdx.x>>5), lane = threadIdx.x & 31;
    float4 v = reinterpret_cast<const float4*>(x + (size_t)m*128)[lane];
    float s = v.x+v.y+v.z+v.w, q = v.x*v.x+v.y*v.y+v.z*v.z+v.w*v.w;
    #pragma unroll
    for (int o = 16; o > 0; o >>= 1) {
        s += __shfl_xor_sync(~0u, s, o); q += __shfl_xor_sync(~0u, q, o);
    }
    float mu = s*(1.f/128.f), rs = rsqrtf(q*(1.f/128.f) - mu*mu + 1e-5f);
    int d0 = lane*4;
    float o0 = na[d0]*(v.x-mu)*rs + nb[d0],     o1 = na[d0+1]*(v.y-mu)*rs + nb[d0+1];
    float o2 = na[d0+2]*(v.z-mu)*rs + nb[d0+2], o3 = na[d0+3]*(v.w-mu)*rs + nb[d0+3];
    __nv_bfloat16 h[4], l[4];
    split2(o0,h[0],l[0]); split2(o1,h[1],l[1]); split2(o2,h[2],l[2]); split2(o3,h[3],l[3]);
    *reinterpret_cast<uint2*>(g_xh + (size_t)m*128 + d0) = *reinterpret_cast<uint2*>(h);
    *reinterpret_cast<uint2*>(g_xl + (size_t)m*128 + d0) = *reinterpret_cast<uint2*>(l);
}

// ---------------- kernel 2: weight transpose + split ----------------
__global__ void w_prep(const float* Wl, const float* Wlg, const float* Wr,
                       const float* Wrg, const float* Wog, const float* Wo) {
    const float* S[6] = {Wl, Wlg, Wr, Wrg, Wog, Wo};
    const float* s = S[blockIdx.x];
    __nv_bfloat16 *dh = g_wh[blockIdx.x], *dl = g_wl[blockIdx.x];
    for (int i = threadIdx.x; i < 16384; i += 256) {
        int k = i>>7, n = i&127;
        __nv_bfloat16 h, l; split2(s[i], h, l);
        dh[n*128+k] = h; dl[n*128+k] = l;
    }
}

// ---------------- kernel 3: projections ----------------
// smem: AH 0, AL 32768, W1H 65536, W1L 98304, W2H 131072, W2L 163840 (end 196608)
#define P_SZ 196608
__global__ void __launch_bounds__(256) proj_kernel(const float* __restrict__ bl,
        const float* __restrict__ blg, const float* __restrict__ br,
        const float* __restrict__ brg, const float* __restrict__ bog) {
    extern __shared__ char sm[];
    uint32_t sb = s2u(sm);
    int tid = threadIdx.x, wid = tid>>5, lane = tid&31;
    int z = blockIdx.y;
    bool dual = (z < 2);
    int wi = z*2;
    const float* b1 = (z==0) ? bl : (z==1) ? br : bog;
    const float* b2 = (z==0) ? blg : brg;

    ldt(sm, 65536, g_wh[wi], tid);
    ldt(sm, 98304, g_wl[wi], tid);
    if (dual) { ldt(sm, 131072, g_wh[wi+1], tid); ldt(sm, 163840, g_wl[wi+1], tid); }

    int mw = (wid&3)*32, nw = (wid>>2)*64;

    for (int t = 0; t < 8; t++) {
        __syncthreads();
        size_t abase = ((size_t)blockIdx.x*8 + t)*128*128;
        ldt(sm, 0,     g_xh + abase, tid);
        ldt(sm, 32768, g_xl + abase, tid);
        __syncthreads();

        float acc1[2][8][4] = {}, acc2[2][8][4] = {};
        #pragma unroll
        for (int pass = 0; pass < 3; pass++) {
            uint32_t ab = (pass==2) ? 32768u : 0u;
            uint32_t w1 = (pass==1) ? 98304u : 65536u;
            uint32_t w2 = (pass==1) ? 163840u : 131072u;
            #pragma unroll
            for (int ks = 0; ks < 8; ks++) {
                uint32_t a[2][4];
                #pragma unroll
                for (int mu = 0; mu < 2; mu++) {
                    int rr = mw + mu*16 + (lane&7) + ((lane>>3)&1)*8;
                    int kg = ks*2 + (lane>>4);
                    ldsm4(a[mu], sb + ab + sw(rr, kg));
                }
                uint32_t bf1[4][4], bf2[4][4];
                #pragma unroll
                for (int p = 0; p < 4; p++) {
                    int rr = nw + p*16 + (lane&7) + ((lane>>4)&1)*8;
                    int kg = ks*2 + ((lane>>3)&1);
                    ldsm4(bf1[p], sb + w1 + sw(rr, kg));
                    if (dual) ldsm4(bf2[p], sb + w2 + sw(rr, kg));
                }
                #pragma unroll
                for (int mu = 0; mu < 2; mu++)
                    #pragma unroll
                    for (int p = 0; p < 4; p++) {
                        mma_bf16(acc1[mu][2*p],   a[mu], &bf1[p][0]);
                        mma_bf16(acc1[mu][2*p+1], a[mu], &bf1[p][2]);
                        if (dual) {
                            mma_bf16(acc2[mu][2*p],   a[mu], &bf2[p][0]);
                            mma_bf16(acc2[mu][2*p+1], a[mu], &bf2[p][2]);
                        }
                    }
            }
        }
        int m0t = (blockIdx.x*8 + t)*128;
        if (dual) {
            __syncthreads();   // everyone done reading A smem
            uint32_t rh[8][4], rl[8][4];
            #pragma unroll
            for (int u = 0; u < 8; u++) {
                int cb = nw + u*8 + 2*(lane&3);
                #pragma unroll
                for (int mu = 0; mu < 2; mu++) {
                    float v0 = (acc1[mu][u][0] + b1[cb])   * sigf(acc2[mu][u][0] + b2[cb]);
                    float v1 = (acc1[mu][u][1] + b1[cb+1]) * sigf(acc2[mu][u][1] + b2[cb+1]);
                    float v2 = (acc1[mu][u][2] + b1[cb])   * sigf(acc2[mu][u][2] + b2[cb]);
                    float v3 = (acc1[mu][u][3] + b1[cb+1]) * sigf(acc2[mu][u][3] + b2[cb+1]);
                    float h0 = bfr(v0), h1 = bfr(v1), h2 = bfr(v2), h3 = bfr(v3);
                    rh[u][mu*2]   = pk(h0, h1);
                    rh[u][mu*2+1] = pk(h2, h3);
                    rl[u][mu*2]   = pk(v0-h0, v1-h1);
                    rl[u][mu*2+1] = pk(v2-h2, v3-h3);
                }
            }
            #pragma unroll
            for (int u = 0; u < 8; u++) {
                int row = nw + u*8 + (lane&7);
                int g = (mw>>3) + (lane>>3);
                stsm4t(sb + 0     + sw(row, g), rh[u]);
                stsm4t(sb + 32768 + sw(row, g), rl[u]);
            }
            __syncthreads();
            __nv_bfloat16* dh = (z==0) ? g_lh : g_rh;
            __nv_bfloat16* dl = (z==0) ? g_ll : g_rl;
            #pragma unroll
            for (int it = 0; it < 8; it++) {
                int c = it*16 + wid*2 + (lane>>4);
                int g = lane & 15;
                uint4 vh = *reinterpret_cast<uint4*>(sm + 0     + sw(c, g));
                uint4 vl = *reinterpret_cast<uint4*>(sm + 32768 + sw(c, g));
                *reinterpret_cast<uint4*>(dh + (size_t)c*MROWS + m0t + g*8) = vh;
                *reinterpret_cast<uint4*>(dl + (size_t)c*MROWS + m0t + g*8) = vl;
            }
        } else {
            #pragma unroll
            for (int mu = 0; mu < 2; mu++) {
                int r0 = m0t + mw + mu*16 + (lane>>2);
                #pragma unroll
                for (int u = 0; u < 8; u++) {
                    int cb = nw + u*8 + 2*(lane&3);
                    float2 v01, v23;
                    v01.x = sigf(acc1[mu][u][0] + b1[cb]);
                    v01.y = sigf(acc1[mu][u][1] + b1[cb+1]);
                    v23.x = sigf(acc1[mu][u][2] + b1[cb]);
                    v23.y = sigf(acc1[mu][u][3] + b1[cb+1]);
                    *reinterpret_cast<float2*>(g_gate + (size_t)r0*128 + cb)     = v01;
                    *reinterpret_cast<float2*>(g_gate + (size_t)(r0+8)*128 + cb) = v23;
                }
            }
        }
    }
}

// ---------------- kernel 4: einsum ----------------
// per CTA: d, i0, j0; K=384 in 6 chunks of 64; buf b @ b*65536: RH+0 RL+16K LH+32K LL+48K
#define E_SZ 131072
__device__ __forceinline__ void ein_issue(uint32_t sb, char* sm, int b, size_t base,
                                          int c, int i0, int j0, int tid) {
    #pragma unroll
    for (int i = 0; i < 4; i++) {
        int idx = tid + i*256, r = idx>>4, g = idx&15;
        size_t ro = base + (size_t)(c*64 + r)*384;
        uint32_t so = sb + (uint32_t)b*65536 + sw(r, g);
        cp16(so,         g_rh + ro + i0 + g*8);
        cp16(so + 16384, g_rl + ro + i0 + g*8);
        cp16(so + 32768, g_lh + ro + j0 + g*8);
        cp16(so + 49152, g_ll + ro + j0 + g*8);
    }
    CP_COMMIT();
}
__global__ void __launch_bounds__(256) einsum_kernel() {
    extern __shared__ char sm[];
    uint32_t sb = s2u(sm);
    int tid = threadIdx.x, wid = tid>>5, lane = tid&31;
    int d = blockIdx.z, i0 = blockIdx.y*128, j0 = blockIdx.x*128;
    const size_t base = (size_t)d * MROWS;
    int mw = (wid&3)*32, nw = (wid>>2)*64;
    float acc[2][8][4] = {};

    ein_issue(sb, sm, 0, base, 0, i0, j0, tid);
    for (int c = 0; c < 6; c++) {
        int b = c & 1;
        if (c < 5) { ein_issue(sb, sm, 1-b, base, c+1, i0, j0, tid); CP_WAIT1(); }
        else CP_WAIT0();
        __syncthreads();
        uint32_t bo = (uint32_t)b*65536;
        #pragma unroll
        for (int pass = 0; pass < 3; pass++) {
            uint32_t ab = bo + ((pass==2) ? 16384u : 0u);
            uint32_t bb = bo + 32768u + ((pass==1) ? 16384u : 0u);
            #pragma unroll
            for (int ks = 0; ks < 4; ks++) {
                uint32_t a[2][4];
                #pragma unroll
                for (int mu = 0; mu < 2; mu++) {
                    int kk = ks*16 + (lane&7) + ((lane>>4)&1)*8;
                    int mg = (mw>>3) + mu*2 + ((lane>>3)&1);
                    ldsm4t(a[mu], sb + ab + sw(kk, mg));
                }
                uint32_t bf[4][4];
                #pragma unroll
                for (int p = 0; p < 4; p++) {
                    int kk = ks*16 + (lane&7) + ((lane>>3)&1)*8;
                    int jg = (nw>>3) + p*2 + ((lane>>4)&1);
                    ldsm4t(bf[p], sb + bb + sw(kk, jg));
                }
                #pragma unroll
                for (int mu = 0; mu < 2; mu++)
                    #pragma unroll
                    for (int p = 0; p < 4; p++) {
                        mma_bf16(acc[mu][2*p],   a[mu], &bf[p][0]);
                        mma_bf16(acc[mu][2*p+1], a[mu], &bf[p][2]);
                    }
            }
        }
        __syncthreads();
    }
    const float s = 1.0f/384.0f;
    float* O = g_tri + base;
    #pragma unroll
    for (int mu = 0; mu < 2; mu++) {
        int i = i0 + mw + mu*16 + (lane>>2);
        #pragma unroll
        for (int u = 0; u < 8; u++) {
            int j = j0 + nw + u*8 + 2*(lane&3);
            float2 v0 = {acc[mu][u][0]*s, acc[mu][u][1]*s};
            float2 v1 = {acc[mu][u][2]*s, acc[mu][u][3]*s};
            *reinterpret_cast<float2*>(O + (size_t)i*384 + j)     = v0;
            *reinterpret_cast<float2*>(O + (size_t)(i+8)*384 + j) = v1;
        }
    }
}

// ---------------- kernel 5: out LN * gate @ Wo + bo ----------------
// smem: AH 0, AL 32768, WH 65536, WL 98304, V @131072 (128*133*4 = 68096) end 199168
#define F_SZ 199168
__global__ void __launch_bounds__(256) final_kernel(const float* __restrict__ ona,
        const float* __restrict__ onb, const float* __restrict__ bo,
        float* __restrict__ out) {
    extern __shared__ char sm[];
    uint32_t sb = s2u(sm);
    int tid = threadIdx.x, wid = tid>>5, lane = tid&31;
    int m0 = blockIdx.x * 128;
    float* V = reinterpret_cast<float*>(sm + 131072);

    ldt(sm, 65536, g_wh[5], tid);
    ldt(sm, 98304, g_wl[5], tid);
    #pragma unroll
    for (int it = 0; it < 16; it++) {
        int idx = tid + it*256, dd = idx>>5, m4 = (idx&31)<<2;
        float4 v = *reinterpret_cast<const float4*>(g_tri + (size_t)dd*MROWS + m0 + m4);
        V[dd*133 + m4] = v.x; V[dd*133 + m4+1] = v.y;
        V[dd*133 + m4+2] = v.z; V[dd*133 + m4+3] = v.w;
    }
    __syncthreads();

    for (int rr = 0; rr < 16; rr++) {
        int r = wid*16 + rr;
        float x0 = V[lane*133 + r],      x1 = V[(lane+32)*133 + r];
        float x2 = V[(lane+64)*133 + r], x3 = V[(lane+96)*133 + r];
        float s = x0+x1+x2+x3, q = x0*x0+x1*x1+x2*x2+x3*x3;
        #pragma unroll
        for (int o = 16; o > 0; o >>= 1) {
            s += __shfl_xor_sync(~0u, s, o); q += __shfl_xor_sync(~0u, q, o);
        }
        float mu = s*(1.f/128.f), rs = rsqrtf(q*(1.f/128.f) - mu*mu + 1e-5f);
        const float* gr = g_gate + (size_t)(m0 + r)*128;
        #pragma unroll
        for (int t = 0; t < 4; t++) {
            int dd = lane + 32*t;
            float xv = (t==0)?x0:(t==1)?x1:(t==2)?x2:x3;
            float v = (ona[dd]*(xv-mu)*rs + onb[dd]) * gr[dd];
            __nv_bfloat16 h, l; split2(v, h, l);
            uint32_t boff = sw(r, dd>>3) + (dd&7)*2;
            *reinterpret_cast<__nv_bfloat16*>(sm + boff) = h;
            *reinterpret_cast<__nv_bfloat16*>(sm + 32768 + boff) = l;
        }
    }
    __syncthreads();

    int mw = (wid&3)*32, nw = (wid>>2)*64;
    float acc[2][8][4] = {};
    #pragma unroll
    for (int pass = 0; pass < 3; pass++) {
        uint32_t ab = (pass==2) ? 32768u : 0u;
        uint32_t wb = (pass==1) ? 98304u : 65536u;
        #pragma unroll
        for (int ks = 0; ks < 8; ks++) {
            uint32_t a[2][4];
            #pragma unroll
            for (int mu = 0; mu < 2; mu++) {
                int rr2 = mw + mu*16 + (lane&7) + ((lane>>3)&1)*8;
                int kg = ks*2 + (lane>>4);
                ldsm4(a[mu], sb + ab + sw(rr2, kg));
            }
            uint32_t bf[4][4];
            #pragma unroll
            for (int p = 0; p < 4; p++) {
                int rr2 = nw + p*16 + (lane&7) + ((lane>>4)&1)*8;
                int kg = ks*2 + ((lane>>3)&1);
                ldsm4(bf[p], sb + wb + sw(rr2, kg));
            }
            #pragma unroll
            for (int mu = 0; mu < 2; mu++)
                #pragma unroll
                for (int p = 0; p < 4; p++) {
                    mma_bf16(acc[mu][2*p],   a[mu], &bf[p][0]);
                    mma_bf16(acc[mu][2*p+1], a[mu], &bf[p][2]);
                }
        }
    }
    #pragma unroll
    for (int mu = 0; mu < 2; mu++) {
        int r0 = m0 + mw + mu*16 + (lane>>2);
        #pragma unroll
        for (int u = 0; u < 8; u++) {
            int cb = nw + u*8 + 2*(lane&3);
            float2 v01 = {acc[mu][u][0] + bo[cb], acc[mu][u][1] + bo[cb+1]};
            float2 v23 = {acc[mu][u][2] + bo[cb], acc[mu][u][3] + bo[cb+1]};
            *reinterpret_cast<float2*>(out + (size_t)r0*128 + cb)     = v01;
            *reinterpret_cast<float2*>(out + (size_t)(r0+8)*128 + cb) = v23;
        }
    }
}

// ---------------------------------------------------------------------------
extern "C" void kernel_launch(void* const* d_in, const int* in_sizes, int n_in,
                              void* d_out, int out_size) {
    const float* x   = (const float*)d_in[0];
    const float* na  = (const float*)d_in[1];
    const float* nb  = (const float*)d_in[2];
    const float* Wl  = (const float*)d_in[3];
    const float* bl  = (const float*)d_in[4];
    const float* Wr  = (const float*)d_in[5];
    const float* br  = (const float*)d_in[6];
    const float* Wlg = (const float*)d_in[7];
    const float* blg = (const float*)d_in[8];
    const float* Wrg = (const float*)d_in[9];
    const float* brg = (const float*)d_in[10];
    const float* Wog = (const float*)d_in[11];
    const float* bog = (const float*)d_in[12];
    const float* ona = (const float*)d_in[13];
    const float* onb = (const float*)d_in[14];
    const float* Wo  = (const float*)d_in[15];
    const float* bo  = (const float*)d_in[16];
    float* out = (float*)d_out;

    cudaFuncSetAttribute(proj_kernel,   cudaFuncAttributeMaxDynamicSharedMemorySize, P_SZ);
    cudaFuncSetAttribute(einsum_kernel, cudaFuncAttributeMaxDynamicSharedMemorySize, E_SZ);
    cudaFuncSetAttribute(final_kernel,  cudaFuncAttributeMaxDynamicSharedMemorySize, F_SZ);

    ln_split<<<MROWS/8, 256>>>(x, na, nb);
    w_prep<<<6, 256>>>(Wl, Wlg, Wr, Wrg, Wog, Wo);
    proj_kernel<<<dim3(144, 3), 256, P_SZ>>>(bl, blg, br, brg, bog);
    einsum_kernel<<<dim3(3, 3, 128), 256, E_SZ>>>();
    final_kernel<<<1152, 256, F_SZ>>>(ona, onb, bo, out);
}

// round 15
// speedup vs baseline: 2.2422x; 1.1086x over previous
#include <cuda_runtime.h>
#include <cuda_bf16.h>
#include <stdint.h>

#define NSEQ 384
#define MROWS 147456

__device__ __align__(16) __nv_bfloat16 g_xh[(size_t)MROWS*128];
__device__ __align__(16) __nv_bfloat16 g_xl[(size_t)MROWS*128];
__device__ __align__(16) __nv_bfloat16 g_lh[(size_t)128*MROWS];  // [d][k*384+j]
__device__ __align__(16) __nv_bfloat16 g_ll[(size_t)128*MROWS];
__device__ __align__(16) __nv_bfloat16 g_rh[(size_t)128*MROWS];  // [d][k*384+i]
__device__ __align__(16) __nv_bfloat16 g_rl[(size_t)128*MROWS];
__device__ __align__(16) float g_gate[(size_t)MROWS*128];        // [m][d]
__device__ __align__(16) float g_tri [(size_t)128*MROWS];        // [d][i*384+j]
__device__ __align__(16) __nv_bfloat16 g_wh[6][16384];           // W^T [n][k]
__device__ __align__(16) __nv_bfloat16 g_wl[6][16384];

__device__ __forceinline__ uint32_t s2u(const void* p) {
    uint32_t a;
    asm("{ .reg .u64 t; cvta.to.shared.u64 t, %1; cvt.u32.u64 %0, t; }" : "=r"(a) : "l"(p));
    return a;
}
__device__ __forceinline__ uint32_t sw(int r, int g) {  // 256B rows, 16B granules
    return (uint32_t)(r*256 + ((g ^ (r & 7)) << 4));
}
__device__ __forceinline__ void mma_bf16(float* c, const uint32_t* a, const uint32_t* b) {
    asm volatile("mma.sync.aligned.m16n8k16.row.col.f32.bf16.bf16.f32 "
        "{%0,%1,%2,%3}, {%4,%5,%6,%7}, {%8,%9}, {%0,%1,%2,%3};"
        : "+f"(c[0]), "+f"(c[1]), "+f"(c[2]), "+f"(c[3])
        : "r"(a[0]), "r"(a[1]), "r"(a[2]), "r"(a[3]), "r"(b[0]), "r"(b[1]));
}
__device__ __forceinline__ void ldsm4(uint32_t* r, uint32_t a) {
    asm volatile("ldmatrix.sync.aligned.m8n8.x4.shared.b16 {%0,%1,%2,%3}, [%4];"
        : "=r"(r[0]),"=r"(r[1]),"=r"(r[2]),"=r"(r[3]) : "r"(a));
}
__device__ __forceinline__ void ldsm4t(uint32_t* r, uint32_t a) {
    asm volatile("ldmatrix.sync.aligned.m8n8.x4.trans.shared.b16 {%0,%1,%2,%3}, [%4];"
        : "=r"(r[0]),"=r"(r[1]),"=r"(r[2]),"=r"(r[3]) : "r"(a));
}
__device__ __forceinline__ void stsm4t(uint32_t a, const uint32_t* r) {
    asm volatile("stmatrix.sync.aligned.m8n8.x4.trans.shared.b16 [%0], {%1,%2,%3,%4};"
        :: "r"(a), "r"(r[0]), "r"(r[1]), "r"(r[2]), "r"(r[3]) : "memory");
}
__device__ __forceinline__ void cp16(uint32_t s, const void* g) {
    asm volatile("cp.async.cg.shared.global [%0], [%1], 16;" :: "r"(s), "l"(g));
}
#define CP_COMMIT() asm volatile("cp.async.commit_group;" ::: "memory")
#define CP_WAIT1()  asm volatile("cp.async.wait_group 1;" ::: "memory")
#define CP_WAIT0()  asm volatile("cp.async.wait_group 0;" ::: "memory")

__device__ __forceinline__ float sigf(float x) { return 1.0f/(1.0f+__expf(-x)); }
__device__ __forceinline__ uint32_t pk(float a, float b) {
    __nv_bfloat162 t = __floats2bfloat162_rn(a, b);
    return *reinterpret_cast<uint32_t*>(&t);
}
__device__ __forceinline__ float bfr(float v) { return __bfloat162float(__float2bfloat16(v)); }
__device__ __forceinline__ void split2(float x, __nv_bfloat16& h, __nv_bfloat16& l) {
    h = __float2bfloat16(x);
    l = __float2bfloat16(x - __bfloat162float(h));
}
// load 128x128 bf16 row-major (ld=128) tile into swizzled smem (512 threads)
__device__ __forceinline__ void ldt5(char* sm, uint32_t off, const __nv_bfloat16* src, int tid) {
    #pragma unroll
    for (int i = 0; i < 4; i++) {
        int idx = tid + i*512, r = idx>>4, g = idx&15;
        *reinterpret_cast<uint4*>(sm + off + sw(r,g)) =
            *reinterpret_cast<const uint4*>(src + (size_t)r*128 + g*8);
    }
}

// ---------------- kernel 1: LN + split ----------------
__global__ void ln_split(const float* __restrict__ x, const float* __restrict__ na,
                         const float* __restrict__ nb) {
    int m = blockIdx.x*8 + (threadIdx.x>>5), lane = threadIdx.x & 31;
    float4 v = reinterpret_cast<const float4*>(x + (size_t)m*128)[lane];
    float s = v.x+v.y+v.z+v.w, q = v.x*v.x+v.y*v.y+v.z*v.z+v.w*v.w;
    #pragma unroll
    for (int o = 16; o > 0; o >>= 1) {
        s += __shfl_xor_sync(~0u, s, o); q += __shfl_xor_sync(~0u, q, o);
    }
    float mu = s*(1.f/128.f), rs = rsqrtf(q*(1.f/128.f) - mu*mu + 1e-5f);
    int d0 = lane*4;
    float o0 = na[d0]*(v.x-mu)*rs + nb[d0],     o1 = na[d0+1]*(v.y-mu)*rs + nb[d0+1];
    float o2 = na[d0+2]*(v.z-mu)*rs + nb[d0+2], o3 = na[d0+3]*(v.w-mu)*rs + nb[d0+3];
    __nv_bfloat16 h[4], l[4];
    split2(o0,h[0],l[0]); split2(o1,h[1],l[1]); split2(o2,h[2],l[2]); split2(o3,h[3],l[3]);
    *reinterpret_cast<uint2*>(g_xh + (size_t)m*128 + d0) = *reinterpret_cast<uint2*>(h);
    *reinterpret_cast<uint2*>(g_xl + (size_t)m*128 + d0) = *reinterpret_cast<uint2*>(l);
}

// ---------------- kernel 2: weight transpose + split ----------------
__global__ void w_prep(const float* Wl, const float* Wlg, const float* Wr,
                       const float* Wrg, const float* Wog, const float* Wo) {
    const float* S[6] = {Wl, Wlg, Wr, Wrg, Wog, Wo};
    const float* s = S[blockIdx.x];
    __nv_bfloat16 *dh = g_wh[blockIdx.x], *dl = g_wl[blockIdx.x];
    for (int i = threadIdx.x; i < 16384; i += 256) {
        int k = i>>7, n = i&127;
        __nv_bfloat16 h, l; split2(s[i], h, l);
        dh[n*128+k] = h; dl[n*128+k] = l;
    }
}

// ---------------- kernel 3: projections (512 thr, 32x32 warp tiles) --------
// smem: AH 0, AL 32768, W1H 65536, W1L 98304, W2H 131072, W2L 163840
#define P_SZ 196608
__global__ void __launch_bounds__(512, 1) proj_kernel(const float* __restrict__ bl,
        const float* __restrict__ blg, const float* __restrict__ br,
        const float* __restrict__ brg, const float* __restrict__ bog) {
    extern __shared__ char sm[];
    uint32_t sb = s2u(sm);
    int tid = threadIdx.x, wid = tid>>5, lane = tid&31;
    int z = blockIdx.y;
    bool dual = (z < 2);
    int wi = z*2;
    const float* b1 = (z==0) ? bl : (z==1) ? br : bog;
    const float* b2 = (z==0) ? blg : brg;

    ldt5(sm, 65536, g_wh[wi], tid);
    ldt5(sm, 98304, g_wl[wi], tid);
    if (dual) { ldt5(sm, 131072, g_wh[wi+1], tid); ldt5(sm, 163840, g_wl[wi+1], tid); }

    int wm = wid & 3, wn = wid >> 2;       // 4 x 4 warp grid
    int mw = wm*32, nw = wn*32;

    for (int t = 0; t < 8; t++) {
        __syncthreads();
        size_t abase = ((size_t)blockIdx.x*8 + t)*128*128;
        ldt5(sm, 0,     g_xh + abase, tid);
        ldt5(sm, 32768, g_xl + abase, tid);
        __syncthreads();

        float acc1[2][4][4] = {}, acc2[2][4][4] = {};
        #pragma unroll
        for (int pass = 0; pass < 3; pass++) {
            uint32_t ab = (pass==2) ? 32768u : 0u;
            uint32_t w1 = (pass==1) ? 98304u : 65536u;
            uint32_t w2 = (pass==1) ? 163840u : 131072u;
            #pragma unroll
            for (int ks = 0; ks < 8; ks++) {
                uint32_t a[2][4];
                #pragma unroll
                for (int mu = 0; mu < 2; mu++) {
                    int rr = mw + mu*16 + (lane&7) + ((lane>>3)&1)*8;
                    int kg = ks*2 + (lane>>4);
                    ldsm4(a[mu], sb + ab + sw(rr, kg));
                }
                uint32_t bf1[2][4], bf2[2][4];
                #pragma unroll
                for (int p = 0; p < 2; p++) {
                    int rr = nw + p*16 + (lane&7) + ((lane>>4)&1)*8;
                    int kg = ks*2 + ((lane>>3)&1);
                    ldsm4(bf1[p], sb + w1 + sw(rr, kg));
                    if (dual) ldsm4(bf2[p], sb + w2 + sw(rr, kg));
                }
                #pragma unroll
                for (int mu = 0; mu < 2; mu++)
                    #pragma unroll
                    for (int p = 0; p < 2; p++) {
                        mma_bf16(acc1[mu][2*p],   a[mu], &bf1[p][0]);
                        mma_bf16(acc1[mu][2*p+1], a[mu], &bf1[p][2]);
                        if (dual) {
                            mma_bf16(acc2[mu][2*p],   a[mu], &bf2[p][0]);
                            mma_bf16(acc2[mu][2*p+1], a[mu], &bf2[p][2]);
                        }
                    }
            }
        }
        int m0t = (blockIdx.x*8 + t)*128;
        if (dual) {
            __syncthreads();   // done reading A smem; reuse as transpose staging
            uint32_t rh[4][4], rl[4][4];
            #pragma unroll
            for (int u = 0; u < 4; u++) {
                int cb = nw + u*8 + 2*(lane&3);
                #pragma unroll
                for (int mu = 0; mu < 2; mu++) {
                    float v0 = (acc1[mu][u][0] + b1[cb])   * sigf(acc2[mu][u][0] + b2[cb]);
                    float v1 = (acc1[mu][u][1] + b1[cb+1]) * sigf(acc2[mu][u][1] + b2[cb+1]);
                    float v2 = (acc1[mu][u][2] + b1[cb])   * sigf(acc2[mu][u][2] + b2[cb]);
                    float v3 = (acc1[mu][u][3] + b1[cb+1]) * sigf(acc2[mu][u][3] + b2[cb+1]);
                    float h0 = bfr(v0), h1 = bfr(v1), h2 = bfr(v2), h3 = bfr(v3);
                    rh[u][mu*2]   = pk(h0, h1);
                    rh[u][mu*2+1] = pk(h2, h3);
                    rl[u][mu*2]   = pk(v0-h0, v1-h1);
                    rl[u][mu*2+1] = pk(v2-h2, v3-h3);
                }
            }
            #pragma unroll
            for (int u = 0; u < 4; u++) {
                int row = nw + u*8 + (lane&7);
                int g = wm*4 + (lane>>3);
                stsm4t(sb + 0     + sw(row, g), rh[u]);
                stsm4t(sb + 32768 + sw(row, g), rl[u]);
            }
            __syncthreads();
            __nv_bfloat16* dh = (z==0) ? g_lh : g_rh;
            __nv_bfloat16* dl = (z==0) ? g_ll : g_rl;
            #pragma unroll
            for (int it = 0; it < 4; it++) {
                int idx = tid + it*512;
                int c = idx>>4, g = idx&15;
                uint4 vh = *reinterpret_cast<uint4*>(sm + 0     + sw(c, g));
                uint4 vl = *reinterpret_cast<uint4*>(sm + 32768 + sw(c, g));
                *reinterpret_cast<uint4*>(dh + (size_t)c*MROWS + m0t + g*8) = vh;
                *reinterpret_cast<uint4*>(dl + (size_t)c*MROWS + m0t + g*8) = vl;
            }
        } else {
            #pragma unroll
            for (int mu = 0; mu < 2; mu++) {
                int r0 = m0t + mw + mu*16 + (lane>>2);
                #pragma unroll
                for (int u = 0; u < 4; u++) {
                    int cb = nw + u*8 + 2*(lane&3);
                    float2 v01, v23;
                    v01.x = sigf(acc1[mu][u][0] + b1[cb]);
                    v01.y = sigf(acc1[mu][u][1] + b1[cb+1]);
                    v23.x = sigf(acc1[mu][u][2] + b1[cb]);
                    v23.y = sigf(acc1[mu][u][3] + b1[cb+1]);
                    *reinterpret_cast<float2*>(g_gate + (size_t)r0*128 + cb)     = v01;
                    *reinterpret_cast<float2*>(g_gate + (size_t)(r0+8)*128 + cb) = v23;
                }
            }
        }
    }
}

// ---------------- kernel 4: einsum (512 thr, 32x32 warp tiles) -------------
// buf b @ b*65536: RH+0 RL+16K LH+32K LL+48K
#define E_SZ 131072
__device__ __forceinline__ void ein_issue(uint32_t sb, int b, size_t base,
                                          int c, int i0, int j0, int tid) {
    #pragma unroll
    for (int i = 0; i < 2; i++) {
        int idx = tid + i*512, r = idx>>4, g = idx&15;
        size_t ro = base + (size_t)(c*64 + r)*384;
        uint32_t so = sb + (uint32_t)b*65536 + sw(r, g);
        cp16(so,         g_rh + ro + i0 + g*8);
        cp16(so + 16384, g_rl + ro + i0 + g*8);
        cp16(so + 32768, g_lh + ro + j0 + g*8);
        cp16(so + 49152, g_ll + ro + j0 + g*8);
    }
    CP_COMMIT();
}
__global__ void __launch_bounds__(512, 1) einsum_kernel() {
    extern __shared__ char sm[];
    uint32_t sb = s2u(sm);
    int tid = threadIdx.x, wid = tid>>5, lane = tid&31;
    int d = blockIdx.z, i0 = blockIdx.y*128, j0 = blockIdx.x*128;
    const size_t base = (size_t)d * MROWS;
    int wm = wid & 3, wn = wid >> 2;
    int mw = wm*32, nw = wn*32;
    float acc[2][4][4] = {};

    ein_issue(sb, 0, base, 0, i0, j0, tid);
    for (int c = 0; c < 6; c++) {
        int b = c & 1;
        if (c < 5) { ein_issue(sb, 1-b, base, c+1, i0, j0, tid); CP_WAIT1(); }
        else CP_WAIT0();
        __syncthreads();
        uint32_t bo = (uint32_t)b*65536;
        #pragma unroll
        for (int pass = 0; pass < 3; pass++) {
            uint32_t ab = bo + ((pass==2) ? 16384u : 0u);
            uint32_t bb = bo + 32768u + ((pass==1) ? 16384u : 0u);
            #pragma unroll
            for (int ks = 0; ks < 4; ks++) {
                uint32_t a[2][4];
                #pragma unroll
                for (int mu = 0; mu < 2; mu++) {
                    int kk = ks*16 + (lane&7) + ((lane>>4)&1)*8;
                    int mg = wm*4 + mu*2 + ((lane>>3)&1);
                    ldsm4t(a[mu], sb + ab + sw(kk, mg));
                }
                uint32_t bf[2][4];
                #pragma unroll
                for (int p = 0; p < 2; p++) {
                    int kk = ks*16 + (lane&7) + ((lane>>3)&1)*8;
                    int jg = wn*4 + p*2 + ((lane>>4)&1);
                    ldsm4t(bf[p], sb + bb + sw(kk, jg));
                }
                #pragma unroll
                for (int mu = 0; mu < 2; mu++)
                    #pragma unroll
                    for (int p = 0; p < 2; p++) {
                        mma_bf16(acc[mu][2*p],   a[mu], &bf[p][0]);
                        mma_bf16(acc[mu][2*p+1], a[mu], &bf[p][2]);
                    }
            }
        }
        __syncthreads();
    }
    const float s = 1.0f/384.0f;
    float* O = g_tri + base;
    #pragma unroll
    for (int mu = 0; mu < 2; mu++) {
        int i = i0 + mw + mu*16 + (lane>>2);
        #pragma unroll
        for (int u = 0; u < 4; u++) {
            int j = j0 + nw + u*8 + 2*(lane&3);
            float2 v0 = {acc[mu][u][0]*s, acc[mu][u][1]*s};
            float2 v1 = {acc[mu][u][2]*s, acc[mu][u][3]*s};
            *reinterpret_cast<float2*>(O + (size_t)i*384 + j)     = v0;
            *reinterpret_cast<float2*>(O + (size_t)(i+8)*384 + j) = v1;
        }
    }
}

// ---------------- kernel 5: out LN * gate @ Wo + bo (512 thr) --------------
// smem: AH 0, AL 32768, WH 65536, WL 98304, V @131072 (128*133*4 = 68096)
#define F_SZ 199168
__global__ void __launch_bounds__(512, 1) final_kernel(const float* __restrict__ ona,
        const float* __restrict__ onb, const float* __restrict__ bo,
        float* __restrict__ out) {
    extern __shared__ char sm[];
    uint32_t sb = s2u(sm);
    int tid = threadIdx.x, wid = tid>>5, lane = tid&31;
    int m0 = blockIdx.x * 128;
    float* V = reinterpret_cast<float*>(sm + 131072);

    ldt5(sm, 65536, g_wh[5], tid);
    ldt5(sm, 98304, g_wl[5], tid);
    #pragma unroll
    for (int it = 0; it < 8; it++) {
        int idx = tid + it*512, dd = idx>>5, m4 = (idx&31)<<2;
        float4 v = *reinterpret_cast<const float4*>(g_tri + (size_t)dd*MROWS + m0 + m4);
        V[dd*133 + m4] = v.x; V[dd*133 + m4+1] = v.y;
        V[dd*133 + m4+2] = v.z; V[dd*133 + m4+3] = v.w;
    }
    __syncthreads();

    for (int rr = 0; rr < 8; rr++) {
        int r = wid*8 + rr;
        float x0 = V[lane*133 + r],      x1 = V[(lane+32)*133 + r];
        float x2 = V[(lane+64)*133 + r], x3 = V[(lane+96)*133 + r];
        float s = x0+x1+x2+x3, q = x0*x0+x1*x1+x2*x2+x3*x3;
        #pragma unroll
        for (int o = 16; o > 0; o >>= 1) {
            s += __shfl_xor_sync(~0u, s, o); q += __shfl_xor_sync(~0u, q, o);
        }
        float mu = s*(1.f/128.f), rs = rsqrtf(q*(1.f/128.f) - mu*mu + 1e-5f);
        const float* gr = g_gate + (size_t)(m0 + r)*128;
        #pragma unroll
        for (int t = 0; t < 4; t++) {
            int dd = lane + 32*t;
            float xv = (t==0)?x0:(t==1)?x1:(t==2)?x2:x3;
            float v = (ona[dd]*(xv-mu)*rs + onb[dd]) * gr[dd];
            __nv_bfloat16 h, l; split2(v, h, l);
            uint32_t boff = sw(r, dd>>3) + (dd&7)*2;
            *reinterpret_cast<__nv_bfloat16*>(sm + boff) = h;
            *reinterpret_cast<__nv_bfloat16*>(sm + 32768 + boff) = l;
        }
    }
    __syncthreads();

    int wm = wid & 3, wn = wid >> 2;
    int mw = wm*32, nw = wn*32;
    float acc[2][4][4] = {};
    #pragma unroll
    for (int pass = 0; pass < 3; pass++) {
        uint32_t ab = (pass==2) ? 32768u : 0u;
        uint32_t wb = (pass==1) ? 98304u : 65536u;
        #pragma unroll
        for (int ks = 0; ks < 8; ks++) {
            uint32_t a[2][4];
            #pragma unroll
            for (int mu = 0; mu < 2; mu++) {
                int rr2 = mw + mu*16 + (lane&7) + ((lane>>3)&1)*8;
                int kg = ks*2 + (lane>>4);
                ldsm4(a[mu], sb + ab + sw(rr2, kg));
            }
            uint32_t bf[2][4];
            #pragma unroll
            for (int p = 0; p < 2; p++) {
                int rr2 = nw + p*16 + (lane&7) + ((lane>>4)&1)*8;
                int kg = ks*2 + ((lane>>3)&1);
                ldsm4(bf[p], sb + wb + sw(rr2, kg));
            }
            #pragma unroll
            for (int mu = 0; mu < 2; mu++)
                #pragma unroll
                for (int p = 0; p < 2; p++) {
                    mma_bf16(acc[mu][2*p],   a[mu], &bf[p][0]);
                    mma_bf16(acc[mu][2*p+1], a[mu], &bf[p][2]);
                }
        }
    }
    #pragma unroll
    for (int mu = 0; mu < 2; mu++) {
        int r0 = m0 + mw + mu*16 + (lane>>2);
        #pragma unroll
        for (int u = 0; u < 4; u++) {
            int cb = nw + u*8 + 2*(lane&3);
            float2 v01 = {acc[mu][u][0] + bo[cb], acc[mu][u][1] + bo[cb+1]};
            float2 v23 = {acc[mu][u][2] + bo[cb], acc[mu][u][3] + bo[cb+1]};
            *reinterpret_cast<float2*>(out + (size_t)r0*128 + cb)     = v01;
            *reinterpret_cast<float2*>(out + (size_t)(r0+8)*128 + cb) = v23;
        }
    }
}

// ---------------------------------------------------------------------------
extern "C" void kernel_launch(void* const* d_in, const int* in_sizes, int n_in,
                              void* d_out, int out_size) {
    const float* x   = (const float*)d_in[0];
    const float* na  = (const float*)d_in[1];
    const float* nb  = (const float*)d_in[2];
    const float* Wl  = (const float*)d_in[3];
    const float* bl  = (const float*)d_in[4];
    const float* Wr  = (const float*)d_in[5];
    const float* br  = (const float*)d_in[6];
    const float* Wlg = (const float*)d_in[7];
    const float* blg = (const float*)d_in[8];
    const float* Wrg = (const float*)d_in[9];
    const float* brg = (const float*)d_in[10];
    const float* Wog = (const float*)d_in[11];
    const float* bog = (const float*)d_in[12];
    const float* ona = (const float*)d_in[13];
    const float* onb = (const float*)d_in[14];
    const float* Wo  = (const float*)d_in[15];
    const float* bo  = (const float*)d_in[16];
    float* out = (float*)d_out;

    cudaFuncSetAttribute(proj_kernel,   cudaFuncAttributeMaxDynamicSharedMemorySize, P_SZ);
    cudaFuncSetAttribute(einsum_kernel, cudaFuncAttributeMaxDynamicSharedMemorySize, E_SZ);
    cudaFuncSetAttribute(final_kernel,  cudaFuncAttributeMaxDynamicSharedMemorySize, F_SZ);

    ln_split<<<MROWS/8, 256>>>(x, na, nb);
    w_prep<<<6, 256>>>(Wl, Wlg, Wr, Wrg, Wog, Wo);
    proj_kernel<<<dim3(144, 3), 512, P_SZ>>>(bl, blg, br, brg, bog);
    einsum_kernel<<<dim3(3, 3, 128), 512, E_SZ>>>();
    final_kernel<<<1152, 512, F_SZ>>>(ona, onb, bo, out);
}